// round 4
// baseline (speedup 1.0000x reference)
#include <cuda_runtime.h>
#include <cstdint>

// DeepSNNController: 3-layer LIF SNN, T=100 steps, B=4096, dims 9 -> 96 -> 96 -> 48.
// One warp per batch element; membrane state in registers; spikes as warp ballot
// bitmasks; layer matvecs as sparse subset-sums of transposed weight rows in smem.

#define T_STEPS 100
#define BATCH   4096
#define D_IN    9
#define H1      96
#define H3      48
#define BETA    0.92f

#define NWARPS  16
#define THREADS (NWARPS * 32)
#define NBLOCKS (BATCH / NWARPS)

// dynamic smem layout (in floats)
#define OFF_W1T 0
#define OFF_W2T (OFF_W1T + D_IN * H1)         // 864
#define OFF_W3T (OFF_W2T + H1 * H1)           // + 9216
#define W3T_SZ  (H1 * H3 + 32)                // pad: lanes >=16 read row*48+32+lane harmlessly
#define OFF_B1  (OFF_W3T + W3T_SZ)
#define OFF_B2  (OFF_B1 + H1)
#define OFF_B3  (OFF_B2 + H1)
#define SMEM_FLOATS (OFF_B3 + 64)             // b3 padded to 64 with zeros

__global__ __launch_bounds__(THREADS, 2)
void snn_kernel(const float* __restrict__ x,
                const float* __restrict__ W1, const float* __restrict__ b1,
                const float* __restrict__ W2, const float* __restrict__ b2,
                const float* __restrict__ W3, const float* __restrict__ b3,
                float* __restrict__ out_spk, float* __restrict__ out_mem)
{
    extern __shared__ float sm[];
    float* sW1t = sm + OFF_W1T;   // [i][h]  i<9,  h<96
    float* sW2t = sm + OFF_W2T;   // [j][h]  j<96, h<96
    float* sW3t = sm + OFF_W3T;   // [j][h]  j<96, h<48 (+pad)
    float* sb1  = sm + OFF_B1;
    float* sb2  = sm + OFF_B2;
    float* sb3  = sm + OFF_B3;

    const int tid = threadIdx.x;

    // Transpose weights into smem (one-time; L2-cached across blocks).
    for (int idx = tid; idx < D_IN * H1; idx += THREADS) {
        int i = idx / H1, h = idx - i * H1;
        sW1t[idx] = W1[h * D_IN + i];
    }
    for (int idx = tid; idx < H1 * H1; idx += THREADS) {
        int j = idx / H1, h = idx - j * H1;
        sW2t[idx] = W2[h * H1 + j];
    }
    for (int idx = tid; idx < W3T_SZ; idx += THREADS) {
        float v = 0.0f;
        if (idx < H1 * H3) {
            int j = idx / H3, h = idx - j * H3;
            v = W3[h * H1 + j];
        }
        sW3t[idx] = v;
    }
    for (int idx = tid; idx < H1; idx += THREADS) {
        sb1[idx] = b1[idx];
        sb2[idx] = b2[idx];
    }
    for (int idx = tid; idx < 64; idx += THREADS)
        sb3[idx] = (idx < H3) ? b3[idx] : 0.0f;
    __syncthreads();

    const int lane = tid & 31;
    const int wid  = tid >> 5;
    const int b    = blockIdx.x * NWARPS + wid;

    // membrane states: layer1/2 -> h = lane, lane+32, lane+64; layer3 -> h = lane, 32+lane (lane<16)
    float m1a = 0.f, m1b = 0.f, m1c = 0.f;
    float m2a = 0.f, m2b = 0.f, m2c = 0.f;
    float m3a = 0.f, m3b = 0.f;

    const float* xb = x + (size_t)b * D_IN;

    // prefetch t=0 input
    float xv = (lane < D_IN) ? __ldg(xb + lane) : 0.0f;

    for (int t = 0; t < T_STEPS; ++t) {
        unsigned um = __ballot_sync(0xffffffffu, xv != 0.0f);
        // prefetch next timestep's input (hide DRAM/L2 latency behind compute)
        if (t + 1 < T_STEPS)
            xv = (lane < D_IN) ? __ldg(xb + (size_t)(t + 1) * BATCH * D_IN + lane) : 0.0f;

        // ---- layer 1: cur1 = x @ W1.T + b1 (subset sum, ascending i) ----
        float c0 = 0.f, c1 = 0.f, c2 = 0.f;
        #pragma unroll
        for (int i = 0; i < D_IN; ++i) {
            if ((um >> i) & 1u) {           // warp-uniform branch
                const float* w = sW1t + i * H1;
                c0 += w[lane]; c1 += w[lane + 32]; c2 += w[lane + 64];
            }
        }
        c0 += sb1[lane]; c1 += sb1[lane + 32]; c2 += sb1[lane + 64];

        float r;
        r = (m1a > 1.0f) ? 1.0f : 0.0f;  m1a = fmaf(BETA, m1a, c0) - r;
        r = (m1b > 1.0f) ? 1.0f : 0.0f;  m1b = fmaf(BETA, m1b, c1) - r;
        r = (m1c > 1.0f) ? 1.0f : 0.0f;  m1c = fmaf(BETA, m1c, c2) - r;
        unsigned s0 = __ballot_sync(0xffffffffu, m1a > 1.0f);
        unsigned s1 = __ballot_sync(0xffffffffu, m1b > 1.0f);
        unsigned s2 = __ballot_sync(0xffffffffu, m1c > 1.0f);

        // ---- layer 2: cur2 = s1 @ W2.T + b2 (sparse bit loop, ascending j) ----
        c0 = 0.f; c1 = 0.f; c2 = 0.f;
        unsigned u = s0;
        while (u) {
            int j = __ffs(u) - 1; u &= u - 1u;
            const float* w = sW2t + j * H1;
            c0 += w[lane]; c1 += w[lane + 32]; c2 += w[lane + 64];
        }
        u = s1;
        while (u) {
            int j = __ffs(u) + 31; u &= u - 1u;
            const float* w = sW2t + j * H1;
            c0 += w[lane]; c1 += w[lane + 32]; c2 += w[lane + 64];
        }
        u = s2;
        while (u) {
            int j = __ffs(u) + 63; u &= u - 1u;
            const float* w = sW2t + j * H1;
            c0 += w[lane]; c1 += w[lane + 32]; c2 += w[lane + 64];
        }
        c0 += sb2[lane]; c1 += sb2[lane + 32]; c2 += sb2[lane + 64];

        r = (m2a > 1.0f) ? 1.0f : 0.0f;  m2a = fmaf(BETA, m2a, c0) - r;
        r = (m2b > 1.0f) ? 1.0f : 0.0f;  m2b = fmaf(BETA, m2b, c1) - r;
        r = (m2c > 1.0f) ? 1.0f : 0.0f;  m2c = fmaf(BETA, m2c, c2) - r;
        unsigned q0 = __ballot_sync(0xffffffffu, m2a > 1.0f);
        unsigned q1 = __ballot_sync(0xffffffffu, m2b > 1.0f);
        unsigned q2 = __ballot_sync(0xffffffffu, m2c > 1.0f);

        // ---- layer 3: cur3 = s2 @ W3.T + b3 (48 outputs: h=lane and h=32+lane for lane<16) ----
        float d0 = 0.f, d1 = 0.f;
        u = q0;
        while (u) {
            int j = __ffs(u) - 1; u &= u - 1u;
            const float* w = sW3t + j * H3;
            d0 += w[lane]; d1 += w[32 + lane];
        }
        u = q1;
        while (u) {
            int j = __ffs(u) + 31; u &= u - 1u;
            const float* w = sW3t + j * H3;
            d0 += w[lane]; d1 += w[32 + lane];
        }
        u = q2;
        while (u) {
            int j = __ffs(u) + 63; u &= u - 1u;
            const float* w = sW3t + j * H3;
            d0 += w[lane]; d1 += w[32 + lane];
        }
        d0 += sb3[lane];
        d1 += sb3[32 + lane];   // sb3 padded to 64

        r = (m3a > 1.0f) ? 1.0f : 0.0f;  m3a = fmaf(BETA, m3a, d0) - r;
        r = (m3b > 1.0f) ? 1.0f : 0.0f;  m3b = fmaf(BETA, m3b, d1) - r;
        float spa = (m3a > 1.0f) ? 1.0f : 0.0f;
        float spb = (m3b > 1.0f) ? 1.0f : 0.0f;

        // ---- record (streaming stores; outputs never re-read) ----
        size_t o = ((size_t)t * BATCH + b) * H3;
        __stcs(out_spk + o + lane, spa);
        __stcs(out_mem + o + lane, m3a);
        if (lane < 16) {
            __stcs(out_spk + o + 32 + lane, spb);
            __stcs(out_mem + o + 32 + lane, m3b);
        }
    }
}

extern "C" void kernel_launch(void* const* d_in, const int* in_sizes, int n_in,
                              void* d_out, int out_size)
{
    const float* x  = (const float*)d_in[0];
    const float* W1 = (const float*)d_in[1];
    const float* b1 = (const float*)d_in[2];
    const float* W2 = (const float*)d_in[3];
    const float* b2 = (const float*)d_in[4];
    const float* W3 = (const float*)d_in[5];
    const float* b3 = (const float*)d_in[6];

    float* out_spk = (float*)d_out;
    float* out_mem = out_spk + (size_t)T_STEPS * BATCH * H3;

    cudaFuncSetAttribute(snn_kernel, cudaFuncAttributeMaxDynamicSharedMemorySize,
                         SMEM_FLOATS * (int)sizeof(float));

    snn_kernel<<<NBLOCKS, THREADS, SMEM_FLOATS * sizeof(float)>>>(
        x, W1, b1, W2, b2, W3, b3, out_spk, out_mem);
}

// round 5
// speedup vs baseline: 1.2340x; 1.2340x over previous
#include <cuda_runtime.h>
#include <cstdint>

// DeepSNNController: 3-layer LIF SNN, T=100, B=4096, dims 9 -> 96 -> 96 -> 48.
// One warp per batch element; membranes in registers; spikes as ballot bitmasks;
// layer matvecs as sparse subset-sums over PACKED weight rows:
//   layer1/2 rows: 128 floats, pos = 4*lane + k  <->  h = lane + 32k (k<3; k=3 pad=0)
//     -> one LDS.128 (ld.shared.v2.b64) + two add.rn.f32x2 per set bit
//   layer3 rows: 64 floats,  pos = 2*lane + k  <->  h = lane + 32k (k<2; pad=0)
//     -> one LDS.64 + one add.rn.f32x2 per set bit
// Packed f32x2 adds are elementwise IEEE fp32 -> bit-exact vs scalar FADD order.
// Grid 296 = 2 x 148 SMs, 14 warps/block -> ~28 balanced tasks per SM.

#define T_STEPS 100
#define BATCH   4096
#define D_IN    9
#define H1      96
#define H3      48
#define BETA    0.92f

#define NWARPS  14
#define THREADS (NWARPS * 32)
#define NBLOCKS 296

// smem layout (floats)
#define ROW1    128
#define ROW3    64
#define OFF_W1T 0
#define OFF_W2T (OFF_W1T + D_IN * ROW1)            // 1152
#define OFF_W3T (OFF_W2T + H1 * ROW1)              // + 12288
#define SMEM_FLOATS (OFF_W3T + H1 * ROW3)          // + 6144 = 19584 floats = 78336 B

__global__ __launch_bounds__(THREADS, 2)
void snn_kernel(const float* __restrict__ x,
                const float* __restrict__ W1, const float* __restrict__ b1,
                const float* __restrict__ W2, const float* __restrict__ b2,
                const float* __restrict__ W3, const float* __restrict__ b3,
                float* __restrict__ out_spk, float* __restrict__ out_mem)
{
    extern __shared__ float sm[];
    float* sW1t = sm + OFF_W1T;
    float* sW2t = sm + OFF_W2T;
    float* sW3t = sm + OFF_W3T;

    const int tid = threadIdx.x;

    // ---- fill packed weight rows (one-time) ----
    for (int idx = tid; idx < D_IN * ROW1; idx += THREADS) {
        int i = idx >> 7, p = idx & 127;
        int ln = p >> 2, k = p & 3;
        float v = 0.0f;
        if (k < 3) v = W1[(ln + 32 * k) * D_IN + i];
        sW1t[idx] = v;
    }
    for (int idx = tid; idx < H1 * ROW1; idx += THREADS) {
        int j = idx >> 7, p = idx & 127;
        int ln = p >> 2, k = p & 3;
        float v = 0.0f;
        if (k < 3) v = W2[(ln + 32 * k) * H1 + j];
        sW2t[idx] = v;
    }
    for (int idx = tid; idx < H1 * ROW3; idx += THREADS) {
        int j = idx >> 6, p = idx & 63;
        int ln = p >> 1, k = p & 1;
        int h = ln + 32 * k;
        float v = 0.0f;
        if (h < H3) v = W3[h * H1 + j];
        sW3t[idx] = v;
    }
    __syncthreads();

    const int lane = tid & 31;
    const int wid  = tid >> 5;
    const int b    = blockIdx.x + NBLOCKS * wid;
    if (b >= BATCH) return;   // whole warp exits together

    // shared-state-space base addresses (per lane)
    unsigned base1 = (unsigned)__cvta_generic_to_shared(sW1t) + (unsigned)lane * 16u;
    unsigned base2 = (unsigned)__cvta_generic_to_shared(sW2t) + (unsigned)lane * 16u;
    unsigned base3 = (unsigned)__cvta_generic_to_shared(sW3t) + (unsigned)lane * 8u;

    // biases in registers (loop-invariant)
    const float bv10 = b1[lane], bv11 = b1[lane + 32], bv12 = b1[lane + 64];
    const float bv20 = b2[lane], bv21 = b2[lane + 32], bv22 = b2[lane + 64];
    const float bv30 = b3[lane];
    const float bv31 = (lane < 16) ? b3[lane + 32] : 0.0f;

    // membrane states
    float m1a = 0.f, m1b = 0.f, m1c = 0.f;
    float m2a = 0.f, m2b = 0.f, m2c = 0.f;
    float m3a = 0.f, m3b = 0.f;

    const float* px = x + (size_t)b * D_IN;              // advances by BATCH*D_IN per t
    float* ps = out_spk + (size_t)b * H3;                // advances by BATCH*H3 per t
    float* pm = out_mem + (size_t)b * H3;

    float xv = (lane < D_IN) ? __ldg(px + lane) : 0.0f;  // t=0 prefetch

    for (int t = 0; t < T_STEPS; ++t) {
        unsigned um = __ballot_sync(0xffffffffu, xv != 0.0f);
        px += (size_t)BATCH * D_IN;
        if (t + 1 < T_STEPS)
            xv = (lane < D_IN) ? __ldg(px + lane) : 0.0f;

        // ---- layer 1: subset sum over active inputs (ascending i) ----
        unsigned long long c01 = 0ull, c23 = 0ull;
        #pragma unroll
        for (int i = 0; i < D_IN; ++i) {
            if ((um >> i) & 1u) {        // warp-uniform
                unsigned long long w0, w1;
                asm volatile("ld.shared.v2.b64 {%0,%1}, [%2];"
                             : "=l"(w0), "=l"(w1) : "r"(base1 + (unsigned)(i * ROW1 * 4)));
                asm("add.rn.f32x2 %0, %0, %1;" : "+l"(c01) : "l"(w0));
                asm("add.rn.f32x2 %0, %0, %1;" : "+l"(c23) : "l"(w1));
            }
        }
        float c0, c1, c2, cjunk;
        asm("mov.b64 {%0,%1}, %2;" : "=f"(c0), "=f"(c1) : "l"(c01));
        asm("mov.b64 {%0,%1}, %2;" : "=f"(c2), "=f"(cjunk) : "l"(c23));
        c0 += bv10; c1 += bv11; c2 += bv12;

        float r;
        r = (m1a > 1.0f) ? 1.0f : 0.0f;  m1a = fmaf(BETA, m1a, c0) - r;
        r = (m1b > 1.0f) ? 1.0f : 0.0f;  m1b = fmaf(BETA, m1b, c1) - r;
        r = (m1c > 1.0f) ? 1.0f : 0.0f;  m1c = fmaf(BETA, m1c, c2) - r;
        unsigned s0 = __ballot_sync(0xffffffffu, m1a > 1.0f);
        unsigned s1 = __ballot_sync(0xffffffffu, m1b > 1.0f);
        unsigned s2 = __ballot_sync(0xffffffffu, m1c > 1.0f);

        // ---- layer 2: sparse bit loops (ascending j across the 3 words) ----
        c01 = 0ull; c23 = 0ull;
        {
            unsigned u = s0;
            while (u) {
                int j = __ffs(u) - 1; u &= u - 1u;
                unsigned long long w0, w1;
                asm volatile("ld.shared.v2.b64 {%0,%1}, [%2];"
                             : "=l"(w0), "=l"(w1) : "r"(base2 + ((unsigned)j << 9)));
                asm("add.rn.f32x2 %0, %0, %1;" : "+l"(c01) : "l"(w0));
                asm("add.rn.f32x2 %0, %0, %1;" : "+l"(c23) : "l"(w1));
            }
            u = s1;
            unsigned base2b = base2 + 32u * 512u;
            while (u) {
                int j = __ffs(u) - 1; u &= u - 1u;
                unsigned long long w0, w1;
                asm volatile("ld.shared.v2.b64 {%0,%1}, [%2];"
                             : "=l"(w0), "=l"(w1) : "r"(base2b + ((unsigned)j << 9)));
                asm("add.rn.f32x2 %0, %0, %1;" : "+l"(c01) : "l"(w0));
                asm("add.rn.f32x2 %0, %0, %1;" : "+l"(c23) : "l"(w1));
            }
            u = s2;
            unsigned base2c = base2 + 64u * 512u;
            while (u) {
                int j = __ffs(u) - 1; u &= u - 1u;
                unsigned long long w0, w1;
                asm volatile("ld.shared.v2.b64 {%0,%1}, [%2];"
                             : "=l"(w0), "=l"(w1) : "r"(base2c + ((unsigned)j << 9)));
                asm("add.rn.f32x2 %0, %0, %1;" : "+l"(c01) : "l"(w0));
                asm("add.rn.f32x2 %0, %0, %1;" : "+l"(c23) : "l"(w1));
            }
        }
        asm("mov.b64 {%0,%1}, %2;" : "=f"(c0), "=f"(c1) : "l"(c01));
        asm("mov.b64 {%0,%1}, %2;" : "=f"(c2), "=f"(cjunk) : "l"(c23));
        c0 += bv20; c1 += bv21; c2 += bv22;

        r = (m2a > 1.0f) ? 1.0f : 0.0f;  m2a = fmaf(BETA, m2a, c0) - r;
        r = (m2b > 1.0f) ? 1.0f : 0.0f;  m2b = fmaf(BETA, m2b, c1) - r;
        r = (m2c > 1.0f) ? 1.0f : 0.0f;  m2c = fmaf(BETA, m2c, c2) - r;
        unsigned q0 = __ballot_sync(0xffffffffu, m2a > 1.0f);
        unsigned q1 = __ballot_sync(0xffffffffu, m2b > 1.0f);
        unsigned q2 = __ballot_sync(0xffffffffu, m2c > 1.0f);

        // ---- layer 3: sparse bit loops, 48 outputs (2 per lane, packed) ----
        unsigned long long d01 = 0ull;
        {
            unsigned u = q0;
            while (u) {
                int j = __ffs(u) - 1; u &= u - 1u;
                unsigned long long w;
                asm volatile("ld.shared.b64 %0, [%1];"
                             : "=l"(w) : "r"(base3 + ((unsigned)j << 8)));
                asm("add.rn.f32x2 %0, %0, %1;" : "+l"(d01) : "l"(w));
            }
            u = q1;
            unsigned base3b = base3 + 32u * 256u;
            while (u) {
                int j = __ffs(u) - 1; u &= u - 1u;
                unsigned long long w;
                asm volatile("ld.shared.b64 %0, [%1];"
                             : "=l"(w) : "r"(base3b + ((unsigned)j << 8)));
                asm("add.rn.f32x2 %0, %0, %1;" : "+l"(d01) : "l"(w));
            }
            u = q2;
            unsigned base3c = base3 + 64u * 256u;
            while (u) {
                int j = __ffs(u) - 1; u &= u - 1u;
                unsigned long long w;
                asm volatile("ld.shared.b64 %0, [%1];"
                             : "=l"(w) : "r"(base3c + ((unsigned)j << 8)));
                asm("add.rn.f32x2 %0, %0, %1;" : "+l"(d01) : "l"(w));
            }
        }
        float d0, d1;
        asm("mov.b64 {%0,%1}, %2;" : "=f"(d0), "=f"(d1) : "l"(d01));
        d0 += bv30; d1 += bv31;

        r = (m3a > 1.0f) ? 1.0f : 0.0f;  m3a = fmaf(BETA, m3a, d0) - r;
        r = (m3b > 1.0f) ? 1.0f : 0.0f;  m3b = fmaf(BETA, m3b, d1) - r;
        float spa = (m3a > 1.0f) ? 1.0f : 0.0f;
        float spb = (m3b > 1.0f) ? 1.0f : 0.0f;

        // ---- record (streaming stores) ----
        __stcs(ps + lane, spa);
        __stcs(pm + lane, m3a);
        if (lane < 16) {
            __stcs(ps + 32 + lane, spb);
            __stcs(pm + 32 + lane, m3b);
        }
        ps += (size_t)BATCH * H3;
        pm += (size_t)BATCH * H3;
    }
}

extern "C" void kernel_launch(void* const* d_in, const int* in_sizes, int n_in,
                              void* d_out, int out_size)
{
    const float* x  = (const float*)d_in[0];
    const float* W1 = (const float*)d_in[1];
    const float* b1 = (const float*)d_in[2];
    const float* W2 = (const float*)d_in[3];
    const float* b2 = (const float*)d_in[4];
    const float* W3 = (const float*)d_in[5];
    const float* b3 = (const float*)d_in[6];

    float* out_spk = (float*)d_out;
    float* out_mem = out_spk + (size_t)T_STEPS * BATCH * H3;

    cudaFuncSetAttribute(snn_kernel, cudaFuncAttributeMaxDynamicSharedMemorySize,
                         SMEM_FLOATS * (int)sizeof(float));

    snn_kernel<<<NBLOCKS, THREADS, SMEM_FLOATS * sizeof(float)>>>(
        x, W1, b1, W2, b2, W3, b3, out_spk, out_mem);
}

// round 6
// speedup vs baseline: 1.2967x; 1.0508x over previous
#include <cuda_runtime.h>
#include <cstdint>

// DeepSNNController: 3-layer LIF SNN, T=100, B=4096, dims 9 -> 96 -> 96 -> 48.
// One warp per batch element; membranes in registers; spikes as ballot bitmasks.
// Layer 1: 512-entry LUT (mask -> cur1 vector incl. bias), prefetched 1 step ahead.
// Layer 2: sparse bit loop over packed 384B rows (pairs h=L,h=L+32 + single h=64+L).
// Layer 3: lane<24 owns h=2L,2L+1; dense 192B rows, LDS.64 + one f32x2 add per bit.
// All per-h summations ascend in j, identical to the reference order (rel_err 0.0).

#define T_STEPS 100
#define BATCH   4096
#define D_IN    9
#define H1      96
#define H3      48
#define BETA    0.92f

#define NWARPS  14
#define THREADS (NWARPS * 32)
#define NBLOCKS 296

// smem (floats): W2 rows 96 floats (384B), W3 rows 48 floats (192B)
#define OFF_W2 0
#define OFF_W3 (96 * 96)
#define SMEM_FLOATS (OFF_W3 + 96 * 48)    // 13824 floats = 55296 B

__device__ float g_lut[512 * 128];        // [mask][p], p = 4*ln+k <-> h = ln+32k (k<3), pad k=3

// ---- LUT precompute: cur1[mask][h] = sum_{i asc, i in mask} W1[h,i] + b1[h] ----
__global__ void lut_kernel(const float* __restrict__ W1, const float* __restrict__ b1)
{
    int mask = blockIdx.x;
    int p = threadIdx.x;             // 0..127
    int ln = p >> 2, k = p & 3;
    float s = 0.0f;
    if (k < 3) {
        int h = ln + 32 * k;
        #pragma unroll
        for (int i = 0; i < D_IN; ++i)
            if ((mask >> i) & 1) s += W1[h * D_IN + i];
        s += b1[h];
    }
    g_lut[mask * 128 + p] = s;
}

__global__ __launch_bounds__(THREADS, 2)
void snn_kernel(const float* __restrict__ x,
                const float* __restrict__ W2, const float* __restrict__ b2,
                const float* __restrict__ W3, const float* __restrict__ b3,
                float* __restrict__ out_spk, float* __restrict__ out_mem)
{
    extern __shared__ float sm[];
    float* sW2 = sm + OFF_W2;
    float* sW3 = sm + OFF_W3;

    const int tid = threadIdx.x;

    // W2 packed: float idx j*96 + p, p<64: h=(p>>1)+32*(p&1); p>=64: h=p
    for (int idx = tid; idx < 96 * 96; idx += THREADS) {
        int j = idx / 96, p = idx - j * 96;
        int h = (p < 64) ? ((p >> 1) + 32 * (p & 1)) : p;
        sW2[idx] = W2[h * H1 + j];
    }
    // W3 dense: float idx j*48 + h
    for (int idx = tid; idx < 96 * 48; idx += THREADS) {
        int j = idx / 48, h = idx - j * 48;
        sW3[idx] = W3[h * H1 + j];
    }
    __syncthreads();

    const int lane = tid & 31;
    const int wid  = tid >> 5;
    const int b    = blockIdx.x + NBLOCKS * wid;
    if (b >= BATCH) return;          // whole warp exits together

    // per-lane smem base addresses
    unsigned smem2 = (unsigned)__cvta_generic_to_shared(sW2);
    unsigned base2p = smem2 + (unsigned)lane * 8u;          // pairs (h=L, h=L+32)
    unsigned base2s = smem2 + 256u + (unsigned)lane * 4u;   // single h=64+L
    const int lsel = (lane < 24) ? lane : (lane - 16);      // dup lanes 24-31 -> broadcast
    unsigned base3 = (unsigned)__cvta_generic_to_shared(sW3) + (unsigned)lsel * 8u;

    // biases in registers
    const float bv20 = b2[lane], bv21 = b2[lane + 32], bv22 = b2[lane + 64];
    const float bv30 = (lane < 24) ? b3[2 * lane] : 0.0f;
    const float bv31 = (lane < 24) ? b3[2 * lane + 1] : 0.0f;

    // membranes and previous-step spikes (floats)
    float m1a = 0.f, m1b = 0.f, m1c = 0.f, k1a = 0.f, k1b = 0.f, k1c = 0.f;
    float m2a = 0.f, m2b = 0.f, m2c = 0.f, k2a = 0.f, k2b = 0.f, k2c = 0.f;
    float m3a = 0.f, m3b = 0.f, k3a = 0.f, k3b = 0.f;

    const float* px = x + (size_t)b * D_IN;
    float2* ps = (float2*)(out_spk + (size_t)b * H3) + lsel;   // 8B per lane (lane<24)
    float2* pm = (float2*)(out_mem + (size_t)b * H3) + lsel;

    // pipeline: xv holds x(t+1); lut holds cur1(t)
    float xv = (lane < D_IN) ? __ldg(px + lane) : 0.0f;        // x(0)
    unsigned um = __ballot_sync(0xffffffffu, xv != 0.0f);
    float4 lut = __ldg((const float4*)(g_lut + (size_t)um * 128) + lane);   // cur1(0)
    px += (size_t)BATCH * D_IN;
    xv = (lane < D_IN) ? __ldg(px + lane) : 0.0f;              // x(1)

    for (int t = 0; t < T_STEPS; ++t) {
        float c0 = lut.x, c1 = lut.y, c2 = lut.z;              // cur1(t), bias included

        // prefetch pipeline for t+1 / t+2
        if (t + 1 < T_STEPS) {
            um = __ballot_sync(0xffffffffu, xv != 0.0f);       // mask of x(t+1)
            lut = __ldg((const float4*)(g_lut + (size_t)um * 128) + lane);
            px += (size_t)BATCH * D_IN;
            if (t + 2 < T_STEPS)
                xv = (lane < D_IN) ? __ldg(px + lane) : 0.0f;  // x(t+2)
        }

        // ---- layer 1 LIF ----
        m1a = fmaf(BETA, m1a, c0) - k1a;
        m1b = fmaf(BETA, m1b, c1) - k1b;
        m1c = fmaf(BETA, m1c, c2) - k1c;
        bool p1a = m1a > 1.0f, p1b = m1b > 1.0f, p1c = m1c > 1.0f;
        k1a = p1a ? 1.0f : 0.0f; k1b = p1b ? 1.0f : 0.0f; k1c = p1c ? 1.0f : 0.0f;
        unsigned s0 = __ballot_sync(0xffffffffu, p1a);
        unsigned s1 = __ballot_sync(0xffffffffu, p1b);
        unsigned s2 = __ballot_sync(0xffffffffu, p1c);

        // ---- layer 2: sparse subset sum, ascending j (j = word*32 + bit) ----
        unsigned long long c01 = 0ull;
        float cs2 = 0.0f;
        {
            unsigned u = s0;
            while (u) {
                int j = __ffs(u) - 1; u &= u - 1u;
                unsigned off = (unsigned)j * 384u;
                unsigned long long w01; float w2v;
                asm volatile("ld.shared.b64 %0, [%1];" : "=l"(w01) : "r"(base2p + off));
                asm volatile("ld.shared.f32 %0, [%1];" : "=f"(w2v) : "r"(base2s + off));
                asm("add.rn.f32x2 %0, %0, %1;" : "+l"(c01) : "l"(w01));
                cs2 += w2v;
            }
            u = s1;
            unsigned bp = base2p + 32u * 384u, bs = base2s + 32u * 384u;
            while (u) {
                int j = __ffs(u) - 1; u &= u - 1u;
                unsigned off = (unsigned)j * 384u;
                unsigned long long w01; float w2v;
                asm volatile("ld.shared.b64 %0, [%1];" : "=l"(w01) : "r"(bp + off));
                asm volatile("ld.shared.f32 %0, [%1];" : "=f"(w2v) : "r"(bs + off));
                asm("add.rn.f32x2 %0, %0, %1;" : "+l"(c01) : "l"(w01));
                cs2 += w2v;
            }
            u = s2;
            bp = base2p + 64u * 384u; bs = base2s + 64u * 384u;
            while (u) {
                int j = __ffs(u) - 1; u &= u - 1u;
                unsigned off = (unsigned)j * 384u;
                unsigned long long w01; float w2v;
                asm volatile("ld.shared.b64 %0, [%1];" : "=l"(w01) : "r"(bp + off));
                asm volatile("ld.shared.f32 %0, [%1];" : "=f"(w2v) : "r"(bs + off));
                asm("add.rn.f32x2 %0, %0, %1;" : "+l"(c01) : "l"(w01));
                cs2 += w2v;
            }
        }
        asm("mov.b64 {%0,%1}, %2;" : "=f"(c0), "=f"(c1) : "l"(c01));
        c0 += bv20; c1 += bv21; c2 = cs2 + bv22;

        // ---- layer 2 LIF ----
        m2a = fmaf(BETA, m2a, c0) - k2a;
        m2b = fmaf(BETA, m2b, c1) - k2b;
        m2c = fmaf(BETA, m2c, c2) - k2c;
        bool p2a = m2a > 1.0f, p2b = m2b > 1.0f, p2c = m2c > 1.0f;
        k2a = p2a ? 1.0f : 0.0f; k2b = p2b ? 1.0f : 0.0f; k2c = p2c ? 1.0f : 0.0f;
        unsigned q0 = __ballot_sync(0xffffffffu, p2a);
        unsigned q1 = __ballot_sync(0xffffffffu, p2b);
        unsigned q2 = __ballot_sync(0xffffffffu, p2c);

        // ---- layer 3: lane<24 owns h = 2*lane, 2*lane+1; dense 192B rows ----
        unsigned long long d01 = 0ull;
        {
            unsigned u = q0;
            while (u) {
                int j = __ffs(u) - 1; u &= u - 1u;
                unsigned long long w;
                asm volatile("ld.shared.b64 %0, [%1];" : "=l"(w) : "r"(base3 + (unsigned)j * 192u));
                asm("add.rn.f32x2 %0, %0, %1;" : "+l"(d01) : "l"(w));
            }
            u = q1;
            unsigned b3b = base3 + 32u * 192u;
            while (u) {
                int j = __ffs(u) - 1; u &= u - 1u;
                unsigned long long w;
                asm volatile("ld.shared.b64 %0, [%1];" : "=l"(w) : "r"(b3b + (unsigned)j * 192u));
                asm("add.rn.f32x2 %0, %0, %1;" : "+l"(d01) : "l"(w));
            }
            u = q2;
            unsigned b3c = base3 + 64u * 192u;
            while (u) {
                int j = __ffs(u) - 1; u &= u - 1u;
                unsigned long long w;
                asm volatile("ld.shared.b64 %0, [%1];" : "=l"(w) : "r"(b3c + (unsigned)j * 192u));
                asm("add.rn.f32x2 %0, %0, %1;" : "+l"(d01) : "l"(w));
            }
        }
        float d0, d1;
        asm("mov.b64 {%0,%1}, %2;" : "=f"(d0), "=f"(d1) : "l"(d01));
        d0 += bv30; d1 += bv31;

        // ---- layer 3 LIF ----
        m3a = fmaf(BETA, m3a, d0) - k3a;
        m3b = fmaf(BETA, m3b, d1) - k3b;
        k3a = (m3a > 1.0f) ? 1.0f : 0.0f;
        k3b = (m3b > 1.0f) ? 1.0f : 0.0f;

        // ---- record: 8B vector streaming stores, lanes 0..23 cover h=0..47 ----
        if (lane < 24) {
            __stcs(ps, make_float2(k3a, k3b));
            __stcs(pm, make_float2(m3a, m3b));
        }
        ps += (size_t)BATCH * H3 / 2;
        pm += (size_t)BATCH * H3 / 2;
    }
}

extern "C" void kernel_launch(void* const* d_in, const int* in_sizes, int n_in,
                              void* d_out, int out_size)
{
    const float* x  = (const float*)d_in[0];
    const float* W1 = (const float*)d_in[1];
    const float* b1 = (const float*)d_in[2];
    const float* W2 = (const float*)d_in[3];
    const float* b2 = (const float*)d_in[4];
    const float* W3 = (const float*)d_in[5];
    const float* b3 = (const float*)d_in[6];

    float* out_spk = (float*)d_out;
    float* out_mem = out_spk + (size_t)T_STEPS * BATCH * H3;

    lut_kernel<<<512, 128>>>(W1, b1);

    cudaFuncSetAttribute(snn_kernel, cudaFuncAttributeMaxDynamicSharedMemorySize,
                         SMEM_FLOATS * (int)sizeof(float));

    snn_kernel<<<NBLOCKS, THREADS, SMEM_FLOATS * sizeof(float)>>>(
        x, W2, b2, W3, b3, out_spk, out_mem);
}